// round 16
// baseline (speedup 1.0000x reference)
#include <cuda_runtime.h>
#include <math.h>

#define B  32
#define L  2048
#define H  1024
#define K2 2048   // 2*H

#define GS 32     // g-splits for u
#define HS 32     // h-splits for v

// Scratch (no allocations allowed anywhere)
__device__ float g_part_u[GS * B * H];    // 4 MB  (L2-hot)
__device__ float g_u[B * H];              // 128 KB
__device__ float g_part_v[HS * B * K2];   // 8 MB  (L2-hot)
__device__ float g_v[B * K2];             // 256 KB
__device__ float g_scores[B * L];         // 256 KB

// Arrival counters (zero-init; kernels leave them at zero -> replay-safe)
__device__ unsigned cnt_s[B];

// ---------------------------------------------------------------------------
// Kernel 1 (IDENTICAL to R13): partial u[b,h] = sum_{g in 32-chunk} hid*aW.
// grid (8, 32) = 256 blocks, block 128. Batch-32 aW loads before any FMA.
// Prefetches rW (8 MB) + enc batches 0..3 into L2.
// ---------------------------------------------------------------------------
__global__ void k_u_partial(const float* __restrict__ hid,
                            const float* __restrict__ aW,
                            const float* __restrict__ rW,
                            const float* __restrict__ enc) {
    {
        const int gt = (blockIdx.y * 8 + blockIdx.x) * 128 + threadIdx.x;
        const float* p = rW + (size_t)gt * 64;
        asm volatile("prefetch.global.L2 [%0];" :: "l"(p));
        asm volatile("prefetch.global.L2 [%0];" :: "l"(p + 32));
#pragma unroll
        for (int j = 0; j < 16; j++) {
            const int g   = gt + j * 32768;
            const int l   = g >> 8;
            const int rem = g & 255;
            const int bb  = rem >> 6;
            const int off = rem & 63;
            const float* q = enc + ((size_t)(l * 32 + bb) * K2) + off * 32;
            asm volatile("prefetch.global.L2 [%0];" :: "l"(q));
        }
    }

    const int h  = blockIdx.x * 128 + threadIdx.x;
    const int g0 = blockIdx.y * 32;

    float a[32];
    {
        const float* ap = aW + (size_t)g0 * H + h;
#pragma unroll
        for (int j = 0; j < 32; j++) a[j] = ap[(size_t)j * H];
    }

    __shared__ float4 s_hid[B][8];                  // 4 KB
    for (int i = threadIdx.x; i < B * 8; i += 128) {
        int b = i >> 3, c = i & 7;
        s_hid[b][c] = ((const float4*)(hid + b * H + g0))[c];
    }
    __syncthreads();

    float acc[B];
#pragma unroll
    for (int b = 0; b < B; b++) acc[b] = 0.f;
#pragma unroll
    for (int c = 0; c < 8; c++) {
#pragma unroll
        for (int b = 0; b < B; b++) {
            float4 h4 = s_hid[b][c];
            acc[b] = fmaf(a[4 * c + 0], h4.x, fmaf(a[4 * c + 1], h4.y,
                      fmaf(a[4 * c + 2], h4.z, fmaf(a[4 * c + 3], h4.w, acc[b]))));
        }
    }
    float* outp = g_part_u + (size_t)blockIdx.y * (B * H) + h;
#pragma unroll
    for (int b = 0; b < B; b++) outp[b * H] = acc[b];
}

// ---------------------------------------------------------------------------
// Kernel 2 (IDENTICAL to R13): u = sum over GS=32 partials, lane-split 4x8.
// ---------------------------------------------------------------------------
__global__ void k_u_reduce() {
    const int t = blockIdx.x * 128 + threadIdx.x;   // 32768 threads
    const int o = t >> 2;
    const int p = (t & 3) * 8;
    const float4* base = (const float4*)g_part_u + o;
    float4 s = make_float4(0.f, 0.f, 0.f, 0.f);
#pragma unroll
    for (int j = 0; j < 8; j++) {
        float4 x = base[(size_t)(p + j) * (B * H / 4)];
        s.x += x.x; s.y += x.y; s.z += x.z; s.w += x.w;
    }
#pragma unroll
    for (int off = 1; off <= 2; off <<= 1) {
        s.x += __shfl_xor_sync(0xffffffffu, s.x, off);
        s.y += __shfl_xor_sync(0xffffffffu, s.y, off);
        s.z += __shfl_xor_sync(0xffffffffu, s.z, off);
        s.w += __shfl_xor_sync(0xffffffffu, s.w, off);
    }
    if ((t & 3) == 0) ((float4*)g_u)[o] = s;
}

// ---------------------------------------------------------------------------
// Kernel 3 (IDENTICAL to R13): partial v = u * rW chunk, batch-32 rW loads.
// grid (16, 32) = 512 blocks, block 128.
// ---------------------------------------------------------------------------
__global__ void k_v_partial(const float* __restrict__ rW) {
    const int k  = blockIdx.x * 128 + threadIdx.x;
    const int h0 = blockIdx.y * 32;

    float r[32];
    {
        const float* rp = rW + (size_t)h0 * K2 + k;
#pragma unroll
        for (int j = 0; j < 32; j++) r[j] = rp[(size_t)j * K2];
    }

    __shared__ float4 s_u[B][8];                    // 4 KB
    for (int i = threadIdx.x; i < B * 8; i += 128) {
        int b = i >> 3, c = i & 7;
        s_u[b][c] = ((const float4*)(g_u + b * H + h0))[c];
    }
    __syncthreads();

    float acc[B];
#pragma unroll
    for (int b = 0; b < B; b++) acc[b] = 0.f;
#pragma unroll
    for (int c = 0; c < 8; c++) {
#pragma unroll
        for (int b = 0; b < B; b++) {
            float4 u4 = s_u[b][c];
            acc[b] = fmaf(r[4 * c + 0], u4.x, fmaf(r[4 * c + 1], u4.y,
                      fmaf(r[4 * c + 2], u4.z, fmaf(r[4 * c + 3], u4.w, acc[b]))));
        }
    }
    float* outp = g_part_v + (size_t)blockIdx.y * (B * K2) + k;
#pragma unroll
    for (int b = 0; b < B; b++) outp[b * K2] = acc[b];
}

// ---------------------------------------------------------------------------
// Kernel 4 (IDENTICAL to R13): v = sum over HS=32 partials, lane-split 4x8.
// ---------------------------------------------------------------------------
__global__ void k_v_reduce() {
    const int t = blockIdx.x * 128 + threadIdx.x;   // 65536 threads
    const int o = t >> 2;
    const int p = (t & 3) * 8;
    const float4* base = (const float4*)g_part_v + o;
    float4 s = make_float4(0.f, 0.f, 0.f, 0.f);
#pragma unroll
    for (int j = 0; j < 8; j++) {
        float4 x = base[(size_t)(p + j) * (B * K2 / 4)];
        s.x += x.x; s.y += x.y; s.z += x.z; s.w += x.w;
    }
#pragma unroll
    for (int off = 1; off <= 2; off <<= 1) {
        s.x += __shfl_xor_sync(0xffffffffu, s.x, off);
        s.y += __shfl_xor_sync(0xffffffffu, s.y, off);
        s.z += __shfl_xor_sync(0xffffffffu, s.z, off);
        s.w += __shfl_xor_sync(0xffffffffu, s.w, off);
    }
    if ((t & 3) == 0) ((float4*)g_v)[o] = s;
}

// ---------------------------------------------------------------------------
// Kernel 5 (HBM-bound): scores[b,l] = v[b] . enc[l,b,:].
// NEW: grid (L/16, B) -- each warp does 2 SEQUENTIAL rows with the proven
// 16-load-batch body, so the 8 KB sv staging + syncthreads is amortized over
// 16 rows/block instead of 8 (halves per-row dead time). Row loop kept
// sequential (#pragma unroll 1) to preserve the 32-reg rolling-window
// schedule. Softmax tail counter-elected as before (threshold L/16).
// ---------------------------------------------------------------------------
__global__ void __launch_bounds__(256, 8) k_scores(const float* __restrict__ enc,
                                                   float* __restrict__ out) {
    const int b    = blockIdx.y;
    const int w    = threadIdx.x >> 5;
    const int lane = threadIdx.x & 31;

    __shared__ float4 sv[K2 / 4];                   // 8 KB
    const float4* v4 = (const float4*)(g_v + b * K2);
    for (int i = threadIdx.x; i < K2 / 4; i += 256) sv[i] = v4[i];
    __syncthreads();

    const int l0 = blockIdx.x * 16 + w * 2;
#pragma unroll 1
    for (int r = 0; r < 2; r++) {
        const int l = l0 + r;
        const float4* e4 = (const float4*)(enc + ((size_t)l * B + b) * K2);

        float4 e[16];
#pragma unroll
        for (int j = 0; j < 16; j++) e[j] = __ldcs(&e4[lane + 32 * j]);

        float ax = 0.f, ay = 0.f, az = 0.f, aw = 0.f;
#pragma unroll
        for (int j = 0; j < 16; j++) {
            float4 vv = sv[lane + 32 * j];
            ax += e[j].x * vv.x; ay += e[j].y * vv.y;
            az += e[j].z * vv.z; aw += e[j].w * vv.w;
        }
        float acc = (ax + ay) + (az + aw);
#pragma unroll
        for (int o = 16; o; o >>= 1)
            acc += __shfl_xor_sync(0xffffffffu, acc, o);
        if (lane == 0) g_scores[b * L + l] = acc;
    }

    // ---- softmax tail: elect the last-finishing block of this batch ----
    __threadfence();
    __syncthreads();
    __shared__ unsigned s_last;
    if (threadIdx.x == 0)
        s_last = (atomicAdd(&cnt_s[b], 1u) == (L / 16) - 1u) ? 1u : 0u;
    __syncthreads();
    if (!s_last) return;

    if (threadIdx.x == 0) atomicExch(&cnt_s[b], 0u);   // replay-safe reset
    __threadfence();

    const int tid = threadIdx.x;
    __shared__ float s_red[8];

    float vals[8];
    float m = -INFINITY;
#pragma unroll
    for (int i = 0; i < 8; i++) {
        vals[i] = __ldcg(&g_scores[b * L + tid + i * 256]);
        m = fmaxf(m, vals[i]);
    }
#pragma unroll
    for (int o = 16; o; o >>= 1)
        m = fmaxf(m, __shfl_xor_sync(0xffffffffu, m, o));
    if (lane == 0) s_red[w] = m;
    __syncthreads();
    float bm = s_red[0];
#pragma unroll
    for (int i = 1; i < 8; i++) bm = fmaxf(bm, s_red[i]);
    __syncthreads();

    float s = 0.f;
#pragma unroll
    for (int i = 0; i < 8; i++) { vals[i] = expf(vals[i] - bm); s += vals[i]; }
#pragma unroll
    for (int o = 16; o; o >>= 1) s += __shfl_xor_sync(0xffffffffu, s, o);
    if (lane == 0) s_red[w] = s;
    __syncthreads();
    float bs = 0.f;
#pragma unroll
    for (int i = 0; i < 8; i++) bs += s_red[i];

    const float inv = 1.f / bs;
#pragma unroll
    for (int i = 0; i < 8; i++)
        out[b * L + tid + i * 256] = vals[i] * inv;
}

// ---------------------------------------------------------------------------
extern "C" void kernel_launch(void* const* d_in, const int* in_sizes, int n_in,
                              void* d_out, int out_size) {
    const float* hid = (const float*)d_in[0];  // [B, H]
    const float* enc = (const float*)d_in[1];  // [L, B, 2H]
    const float* rW  = (const float*)d_in[2];  // [H, 2H]
    // d_in[3] = reduce_b, d_in[5] = attn_b: constant per batch over l ->
    // invariant under softmax, provably unused.
    const float* aW  = (const float*)d_in[4];  // [H, H]
    float* out = (float*)d_out;                // [B, L]

    k_u_partial<<<dim3(8, GS), 128>>>(hid, aW, rW, enc);
    k_u_reduce<<<256, 128>>>();
    k_v_partial<<<dim3(16, HS), 128>>>(rW);
    k_v_reduce<<<512, 128>>>();
    k_scores<<<dim3(L / 16, B), 256>>>(enc, out);
}

// round 17
// speedup vs baseline: 1.0250x; 1.0250x over previous
#include <cuda_runtime.h>
#include <math.h>

#define B  32
#define L  2048
#define H  1024
#define K2 2048   // 2*H

#define GS 32     // g-splits for u
#define HS 32     // h-splits for v

// Scratch (no allocations allowed anywhere)
__device__ float g_part_u[GS * B * H];    // 4 MB  (L2-hot)
__device__ float g_u[B * H];              // 128 KB
__device__ float g_part_v[HS * B * K2];   // 8 MB  (L2-hot)
__device__ float g_v[B * K2];             // 256 KB
__device__ float g_scores[B * L];         // 256 KB

// Arrival counters (zero-init; kernels leave them at zero -> replay-safe)
__device__ unsigned cnt_s[B];

// ---------------------------------------------------------------------------
// Kernel 1: partial u[b,h] = sum_{g in 32-chunk} hid[b,g]*aW[g,h]
// grid (8, 32) = 256 blocks, block 128. Batch-32 aW loads issued before any
// FMA (max MLP on cold DRAM — the R10 insight that fixed the prologue).
// Prefetches rW (8 MB) into L2 for kernel 3, plus enc batches 0..3 (hint).
// ---------------------------------------------------------------------------
__global__ void k_u_partial(const float* __restrict__ hid,
                            const float* __restrict__ aW,
                            const float* __restrict__ rW,
                            const float* __restrict__ enc) {
    {
        const int gt = (blockIdx.y * 8 + blockIdx.x) * 128 + threadIdx.x;
        // rW: 32768 threads x 64 floats = 8 MB
        const float* p = rW + (size_t)gt * 64;
        asm volatile("prefetch.global.L2 [%0];" :: "l"(p));
        asm volatile("prefetch.global.L2 [%0];" :: "l"(p + 32));
        // enc batches b=0..3 (hint lines for k_scores' first wave)
#pragma unroll
        for (int j = 0; j < 16; j++) {
            const int g   = gt + j * 32768;        // line index
            const int l   = g >> 8;                // 256 lines per l
            const int rem = g & 255;
            const int bb  = rem >> 6;              // batch 0..3
            const int off = rem & 63;              // line within 8 KB row
            const float* q = enc + ((size_t)(l * 32 + bb) * K2) + off * 32;
            asm volatile("prefetch.global.L2 [%0];" :: "l"(q));
        }
    }

    const int h  = blockIdx.x * 128 + threadIdx.x;
    const int g0 = blockIdx.y * 32;

    float a[32];
    {
        const float* ap = aW + (size_t)g0 * H + h;
#pragma unroll
        for (int j = 0; j < 32; j++) a[j] = ap[(size_t)j * H];
    }

    __shared__ float4 s_hid[B][8];                  // 4 KB
    for (int i = threadIdx.x; i < B * 8; i += 128) {
        int b = i >> 3, c = i & 7;
        s_hid[b][c] = ((const float4*)(hid + b * H + g0))[c];
    }
    __syncthreads();

    float acc[B];
#pragma unroll
    for (int b = 0; b < B; b++) acc[b] = 0.f;
#pragma unroll
    for (int c = 0; c < 8; c++) {
#pragma unroll
        for (int b = 0; b < B; b++) {
            float4 h4 = s_hid[b][c];
            acc[b] = fmaf(a[4 * c + 0], h4.x, fmaf(a[4 * c + 1], h4.y,
                      fmaf(a[4 * c + 2], h4.z, fmaf(a[4 * c + 3], h4.w, acc[b]))));
        }
    }
    float* outp = g_part_u + (size_t)blockIdx.y * (B * H) + h;
#pragma unroll
    for (int b = 0; b < B; b++) outp[b * H] = acc[b];
}

// ---------------------------------------------------------------------------
// Kernel 2: u = sum over GS=32 partials. Lane-split 4 threads x 8 loads,
// shfl-combined (deterministic order). 256 blocks x 128 (full SM spread).
// ---------------------------------------------------------------------------
__global__ void k_u_reduce() {
    const int t = blockIdx.x * 128 + threadIdx.x;   // 32768 threads
    const int o = t >> 2;                 // output float4 index (0..8191)
    const int p = (t & 3) * 8;
    const float4* base = (const float4*)g_part_u + o;
    float4 s = make_float4(0.f, 0.f, 0.f, 0.f);
#pragma unroll
    for (int j = 0; j < 8; j++) {
        float4 x = base[(size_t)(p + j) * (B * H / 4)];
        s.x += x.x; s.y += x.y; s.z += x.z; s.w += x.w;
    }
#pragma unroll
    for (int off = 1; off <= 2; off <<= 1) {
        s.x += __shfl_xor_sync(0xffffffffu, s.x, off);
        s.y += __shfl_xor_sync(0xffffffffu, s.y, off);
        s.z += __shfl_xor_sync(0xffffffffu, s.z, off);
        s.w += __shfl_xor_sync(0xffffffffu, s.w, off);
    }
    if ((t & 3) == 0) ((float4*)g_u)[o] = s;
}

// ---------------------------------------------------------------------------
// Kernel 3: partial v[b,k] = sum_{h in 32-chunk} u[b,h] * rW[h,k]
// grid (16, 32) = 512 blocks, block 128. Batch-32 rW loads (L2-hit via
// kernel 1's prefetch) before any FMA.
// ---------------------------------------------------------------------------
__global__ void k_v_partial(const float* __restrict__ rW) {
    const int k  = blockIdx.x * 128 + threadIdx.x;
    const int h0 = blockIdx.y * 32;

    float r[32];
    {
        const float* rp = rW + (size_t)h0 * K2 + k;
#pragma unroll
        for (int j = 0; j < 32; j++) r[j] = rp[(size_t)j * K2];
    }

    __shared__ float4 s_u[B][8];                    // 4 KB
    for (int i = threadIdx.x; i < B * 8; i += 128) {
        int b = i >> 3, c = i & 7;
        s_u[b][c] = ((const float4*)(g_u + b * H + h0))[c];
    }
    __syncthreads();

    float acc[B];
#pragma unroll
    for (int b = 0; b < B; b++) acc[b] = 0.f;
#pragma unroll
    for (int c = 0; c < 8; c++) {
#pragma unroll
        for (int b = 0; b < B; b++) {
            float4 u4 = s_u[b][c];
            acc[b] = fmaf(r[4 * c + 0], u4.x, fmaf(r[4 * c + 1], u4.y,
                      fmaf(r[4 * c + 2], u4.z, fmaf(r[4 * c + 3], u4.w, acc[b]))));
        }
    }
    float* outp = g_part_v + (size_t)blockIdx.y * (B * K2) + k;
#pragma unroll
    for (int b = 0; b < B; b++) outp[b * K2] = acc[b];
}

// ---------------------------------------------------------------------------
// Kernel 4: v = sum over HS=32 partials. Lane-split 4 threads x 8 loads.
// 512 blocks x 128 = 65536 threads (full SM spread).
// ---------------------------------------------------------------------------
__global__ void k_v_reduce() {
    const int t = blockIdx.x * 128 + threadIdx.x;   // 65536 threads
    const int o = t >> 2;                 // output float4 index (0..16383)
    const int p = (t & 3) * 8;
    const float4* base = (const float4*)g_part_v + o;
    float4 s = make_float4(0.f, 0.f, 0.f, 0.f);
#pragma unroll
    for (int j = 0; j < 8; j++) {
        float4 x = base[(size_t)(p + j) * (B * K2 / 4)];
        s.x += x.x; s.y += x.y; s.z += x.z; s.w += x.w;
    }
#pragma unroll
    for (int off = 1; off <= 2; off <<= 1) {
        s.x += __shfl_xor_sync(0xffffffffu, s.x, off);
        s.y += __shfl_xor_sync(0xffffffffu, s.y, off);
        s.z += __shfl_xor_sync(0xffffffffu, s.z, off);
        s.w += __shfl_xor_sync(0xffffffffu, s.w, off);
    }
    if ((t & 3) == 0) ((float4*)g_v)[o] = s;
}

// ---------------------------------------------------------------------------
// Kernel 5 (HBM-bound; measured at the chip's 6.6-6.7 TB/s streaming
// ceiling): scores[b,l] = v[b] . enc[l,b,:] + counter-elected softmax tail.
// One 8 KB row per warp, grid (L/8, B), block 256, launch_bounds(256,8)
// -> 32 regs / ~full occupancy; all 16 LDG.128 per lane batched before
// consumption; __ldcs streaming hint (enc has zero reuse).
// ---------------------------------------------------------------------------
__global__ void __launch_bounds__(256, 8) k_scores(const float* __restrict__ enc,
                                                   float* __restrict__ out) {
    const int b    = blockIdx.y;
    const int w    = threadIdx.x >> 5;
    const int lane = threadIdx.x & 31;

    __shared__ float4 sv[K2 / 4];                   // 8 KB
    const float4* v4 = (const float4*)(g_v + b * K2);
    for (int i = threadIdx.x; i < K2 / 4; i += 256) sv[i] = v4[i];
    __syncthreads();

    const int l = blockIdx.x * 8 + w;
    const float4* e4 = (const float4*)(enc + ((size_t)l * B + b) * K2);

    float4 e[16];
#pragma unroll
    for (int j = 0; j < 16; j++) e[j] = __ldcs(&e4[lane + 32 * j]);

    float ax = 0.f, ay = 0.f, az = 0.f, aw = 0.f;
#pragma unroll
    for (int j = 0; j < 16; j++) {
        float4 vv = sv[lane + 32 * j];
        ax += e[j].x * vv.x; ay += e[j].y * vv.y;
        az += e[j].z * vv.z; aw += e[j].w * vv.w;
    }
    float acc = (ax + ay) + (az + aw);
#pragma unroll
    for (int o = 16; o; o >>= 1)
        acc += __shfl_xor_sync(0xffffffffu, acc, o);
    if (lane == 0) g_scores[b * L + l] = acc;

    // ---- softmax tail: elect the 256th-finishing block of this batch ----
    __threadfence();
    __syncthreads();
    __shared__ unsigned s_last;
    if (threadIdx.x == 0)
        s_last = (atomicAdd(&cnt_s[b], 1u) == (L / 8) - 1u) ? 1u : 0u;
    __syncthreads();
    if (!s_last) return;

    if (threadIdx.x == 0) atomicExch(&cnt_s[b], 0u);   // replay-safe reset
    __threadfence();

    const int tid = threadIdx.x;
    __shared__ float s_red[8];

    float vals[8];
    float m = -INFINITY;
#pragma unroll
    for (int i = 0; i < 8; i++) {
        vals[i] = __ldcg(&g_scores[b * L + tid + i * 256]);
        m = fmaxf(m, vals[i]);
    }
#pragma unroll
    for (int o = 16; o; o >>= 1)
        m = fmaxf(m, __shfl_xor_sync(0xffffffffu, m, o));
    if (lane == 0) s_red[w] = m;
    __syncthreads();
    float bm = s_red[0];
#pragma unroll
    for (int i = 1; i < 8; i++) bm = fmaxf(bm, s_red[i]);
    __syncthreads();

    float s = 0.f;
#pragma unroll
    for (int i = 0; i < 8; i++) { vals[i] = expf(vals[i] - bm); s += vals[i]; }
#pragma unroll
    for (int o = 16; o; o >>= 1) s += __shfl_xor_sync(0xffffffffu, s, o);
    if (lane == 0) s_red[w] = s;
    __syncthreads();
    float bs = 0.f;
#pragma unroll
    for (int i = 0; i < 8; i++) bs += s_red[i];

    const float inv = 1.f / bs;
#pragma unroll
    for (int i = 0; i < 8; i++)
        out[b * L + tid + i * 256] = vals[i] * inv;
}

// ---------------------------------------------------------------------------
extern "C" void kernel_launch(void* const* d_in, const int* in_sizes, int n_in,
                              void* d_out, int out_size) {
    const float* hid = (const float*)d_in[0];  // [B, H]
    const float* enc = (const float*)d_in[1];  // [L, B, 2H]
    const float* rW  = (const float*)d_in[2];  // [H, 2H]
    // d_in[3] = reduce_b, d_in[5] = attn_b: constant per batch over l ->
    // invariant under softmax, provably unused.
    const float* aW  = (const float*)d_in[4];  // [H, H]
    float* out = (float*)d_out;                // [B, L]

    k_u_partial<<<dim3(8, GS), 128>>>(hid, aW, rW, enc);
    k_u_reduce<<<256, 128>>>();
    k_v_partial<<<dim3(16, HS), 128>>>(rW);
    k_v_reduce<<<512, 128>>>();
    k_scores<<<dim3(L / 8, B), 256>>>(enc, out);
}